// round 5
// baseline (speedup 1.0000x reference)
#include <cuda_runtime.h>
#include <math.h>

#define HS   14
#define PX   196
#define SEQ  197
#define PW   16            // padded grid width
#define PSZ  256           // padded grid size (16x16)
#define BIGL 0x3FFFFFFF
#define WPB  8             // warps per block

__global__ __launch_bounds__(256) void blob_loss_kernel(
    const float* __restrict__ dot_qk,
    float* __restrict__ out,
    float inv_n, int ntask)
{
    __shared__ int   lab_s[WPB][PSZ];
    __shared__ float pu_s [WPB][PSZ];

    const int warp = threadIdx.x >> 5;
    const int lane = threadIdx.x & 31;
    const int bh   = blockIdx.x * WPB + warp;
    if (bh >= ntask) return;

    int*   LAB = lab_s[warp];
    float* PU  = pu_s [warp];

    const float* rowp = dot_qk + (size_t)bh * (SEQ * SEQ) + 1;

    // ---- load 196 contiguous floats (lane + 32k), compute padded indices
    float x[7];
    int   pp[7];
    float sum = 0.f;
    #pragma unroll
    for (int r = 0; r < 7; r++) {
        int p   = r * 32 + lane;
        bool ok = (p < PX);
        x[r] = ok ? rowp[p] : 0.f;
        sum += x[r];
        int ri = p / HS, ci = p - ri * HS;
        pp[r] = ok ? ((ri + 1) * PW + ci + 1) : -1;
    }
    #pragma unroll
    for (int o = 16; o; o >>= 1) sum += __shfl_xor_sync(0xffffffffu, sum, o);
    const float m = sum * (1.0f / 196.0f);

    // ---- init padded label grid (BIG border + background) and pu
    #pragma unroll
    for (int r = 0; r < 8; r++) {
        LAB[r * 32 + lane] = BIGL;
        PU [r * 32 + lane] = 0.f;
    }
    __syncwarp();

    // ---- mask, xv (registers), seed labels, B
    float xv[7];
    unsigned mk = 0;
    float Bsum = 0.f;
    #pragma unroll
    for (int r = 0; r < 7; r++) {
        xv[r] = 0.f;
        if (pp[r] >= 0) {
            xv[r] = fmaxf(x[r] - m, 0.f) + 1e-9f;
            if (x[r] > m) {
                mk |= (1u << r);
                Bsum += xv[r];
                LAB[pp[r]] = pp[r];
            }
        }
    }
    #pragma unroll
    for (int o = 16; o; o >>= 1) Bsum += __shfl_xor_sync(0xffffffffu, Bsum, o);
    __syncwarp();

    // ---- connected components: branchless 3x3 min + double pointer-jump,
    //      Jacobi iterations to exact fixpoint (warp-local sync only)
    for (;;) {
        int nl[7];
        #pragma unroll
        for (int r = 0; r < 7; r++) {
            nl[r] = BIGL;
            if (mk & (1u << r)) {
                int q = pp[r];
                int v =        LAB[q - PW - 1];
                v = min(v,     LAB[q - PW    ]);
                v = min(v,     LAB[q - PW + 1]);
                v = min(v,     LAB[q - 1     ]);
                v = min(v,     LAB[q         ]);
                v = min(v,     LAB[q + 1     ]);
                v = min(v,     LAB[q + PW - 1]);
                v = min(v,     LAB[q + PW    ]);
                v = min(v,     LAB[q + PW + 1]);
                v = LAB[v];        // pointer jump 1 (v is a valid masked padded idx)
                v = LAB[v];        // pointer jump 2
                nl[r] = v;
            }
        }
        __syncwarp();
        bool ch = false;
        #pragma unroll
        for (int r = 0; r < 7; r++) {
            if ((mk & (1u << r)) && nl[r] < LAB[pp[r]]) {
                LAB[pp[r]] = nl[r];            // exclusive owner write
                ch = true;
            }
        }
        if (!__any_sync(0xffffffffu, ch)) break;   // vote = sync point
        __syncwarp();
    }
    __syncwarp();

    // ---- per-component sums (warp-private shared atomics)
    #pragma unroll
    for (int r = 0; r < 7; r++)
        if (mk & (1u << r)) atomicAdd(&PU[LAB[pp[r]]], xv[r]);
    __syncwarp();

    // ---- entropy over roots, warp-reduce, one global atomic per warp
    float h = 0.f;
    const float invB = 1.0f / Bsum;
    #pragma unroll
    for (int r = 0; r < 7; r++) {
        if ((mk & (1u << r)) && LAB[pp[r]] == pp[r]) {
            float pn = PU[pp[r]] * invB;
            h -= pn * logf(pn);
        }
    }
    #pragma unroll
    for (int o = 16; o; o >>= 1) h += __shfl_xor_sync(0xffffffffu, h, o);
    if (lane == 0) atomicAdd(out, h * inv_n);
}

extern "C" void kernel_launch(void* const* d_in, const int* in_sizes, int n_in,
                              void* d_out, int out_size)
{
    const float* dq = (const float*)d_in[0];
    float* out = (float*)d_out;
    const int n = in_sizes[0] / (SEQ * SEQ);     // 128*12 = 1536

    cudaMemsetAsync(out, 0, sizeof(float));
    blob_loss_kernel<<<(n + WPB - 1) / WPB, 256>>>(dq, out, 1.0f / (float)n, n);
}

// round 6
// speedup vs baseline: 1.0008x; 1.0008x over previous
#include <cuda_runtime.h>
#include <math.h>

#define HS   14
#define PX   196
#define SEQ  197
#define PW   16            // padded grid width
#define PSZ  256           // padded grid (16x16)
#define BIGL 0x3FFFFFFF
#define NT   224           // 7 warps, 1 pixel per thread

// find root (tree is monotone-decreasing; volatile to force re-reads)
__device__ __forceinline__ int ufind(volatile int* PAR, int a)
{
    int p = PAR[a];
    while (p != a) { a = p; p = PAR[a]; }
    return a;
}

// union by min-root via atomicMin linking (lock-free, single pass)
__device__ __forceinline__ void uunion(int* PAR, int a, int b)
{
    for (;;) {
        a = ufind(PAR, a);
        b = ufind(PAR, b);
        if (a == b) return;
        if (a < b) { int tmp = a; a = b; b = tmp; }   // a = larger root
        int old = atomicMin(&PAR[a], b);
        if (old == a) return;                          // linked a -> b
        a = old;                                       // lost race; follow
    }
}

__global__ __launch_bounds__(NT) void blob_loss_kernel(
    const float* __restrict__ dot_qk,
    float* __restrict__ out,
    float inv_n)
{
    __shared__ int   PAR[PSZ];
    __shared__ float PU [PSZ];
    __shared__ float red[8];
    __shared__ float s_mean, s_B;

    const int t    = threadIdx.x;
    const int warp = t >> 5;
    const int lane = t & 31;
    const int bh   = blockIdx.x;

    // ---- init padded parent grid + component sums (256 slots by 224 threads)
    PAR[t] = BIGL;
    PU [t] = 0.f;
    if (t < PSZ - NT) { PAR[NT + t] = BIGL; PU[NT + t] = 0.f; }

    // ---- load: 196 contiguous floats (row 0, cols 1..196 of this slab)
    const bool ok = (t < PX);
    const float* rowp = dot_qk + (size_t)bh * (SEQ * SEQ) + 1;
    const float x = ok ? rowp[t] : 0.f;

    const int ri = t / HS;
    const int ci = t - ri * HS;
    const int pp = (ri + 1) * PW + ci + 1;   // padded index

    // ---- mean: warp shuffle + cross-warp
    float s = x;
    #pragma unroll
    for (int o = 16; o; o >>= 1) s += __shfl_xor_sync(0xffffffffu, s, o);
    if (lane == 0) red[warp] = s;
    __syncthreads();                                            // B1
    if (t == 0) {
        float a = 0.f;
        #pragma unroll
        for (int w = 0; w < 7; w++) a += red[w];
        s_mean = a * (1.0f / (float)PX);
    }
    __syncthreads();                                            // B2

    const float m   = s_mean;
    const bool  msk = ok && (x > m);
    const float xv  = fmaxf(x - m, 0.f) + 1e-9f;

    // seed parents; reduce B = sum(xv over mask)
    if (msk) PAR[pp] = pp;
    float b = msk ? xv : 0.f;
    #pragma unroll
    for (int o = 16; o; o >>= 1) b += __shfl_xor_sync(0xffffffffu, b, o);
    if (lane == 0) red[warp] = b;
    __syncthreads();                                            // B3

    if (t == 0) {
        float a = 0.f;
        #pragma unroll
        for (int w = 0; w < 7; w++) a += red[w];
        s_B = a;
    }

    // ---- connected components: 4 unions per pixel, single pass
    if (msk) {
        int q;
        q = pp - PW - 1; if (PAR[q] != BIGL) uunion(PAR, pp, q);
        q = pp - PW;     if (PAR[q] != BIGL) uunion(PAR, pp, q);
        q = pp - PW + 1; if (PAR[q] != BIGL) uunion(PAR, pp, q);
        q = pp - 1;      if (PAR[q] != BIGL) uunion(PAR, pp, q);
    }
    __syncthreads();                                            // B4

    // ---- per-component sums
    int root = 0;
    if (msk) {
        root = ufind(PAR, pp);
        atomicAdd(&PU[root], xv);
    }
    __syncthreads();                                            // B5

    // ---- entropy at roots, reduce, one global atomic per CTA
    float h = 0.f;
    if (msk && root == pp) {
        float pn = PU[pp] / s_B;
        h = -pn * logf(pn);
    }
    #pragma unroll
    for (int o = 16; o; o >>= 1) h += __shfl_xor_sync(0xffffffffu, h, o);
    if (lane == 0) red[warp] = h;
    __syncthreads();                                            // B6
    if (t == 0) {
        float a = 0.f;
        #pragma unroll
        for (int w = 0; w < 7; w++) a += red[w];
        atomicAdd(out, a * inv_n);
    }
}

extern "C" void kernel_launch(void* const* d_in, const int* in_sizes, int n_in,
                              void* d_out, int out_size)
{
    const float* dq = (const float*)d_in[0];
    float* out = (float*)d_out;
    const int n = in_sizes[0] / (SEQ * SEQ);   // 128*12 = 1536

    cudaMemsetAsync(out, 0, sizeof(float));
    blob_loss_kernel<<<n, NT>>>(dq, out, 1.0f / (float)n);
}

// round 7
// speedup vs baseline: 1.7127x; 1.7113x over previous
#include <cuda_runtime.h>
#include <math.h>

#define HS   14
#define PX   196
#define SEQ  197
#define FULL 0xFFFFFFFFu

__global__ __launch_bounds__(32) void blob_loss_kernel(
    const float* __restrict__ dot_qk,
    float* __restrict__ out,
    float inv_n, int ntask)
{
    __shared__ float PU[PX];

    const int lane = threadIdx.x;
    const int task = blockIdx.x;
    if (task >= ntask) return;

    const float* rowp = dot_qk + (size_t)task * (SEQ * SEQ) + 1;
    const bool rowok = (lane < HS);
    const float* myrow = rowp + lane * HS;

    // ---- lane r owns row r: 14 register-resident floats
    float x[HS];
    float rs = 0.f;
    #pragma unroll
    for (int c = 0; c < HS; c++) {
        x[c] = rowok ? myrow[c] : 0.f;
        rs += x[c];
    }
    // mean over 196
    float s = rs;
    #pragma unroll
    for (int o = 16; o; o >>= 1) s += __shfl_xor_sync(FULL, s, o);
    const float m = s * (1.0f / 196.0f);

    // ---- mask bits, xv (registers), B
    unsigned mk = 0;
    float xv[HS];
    float b = 0.f;
    #pragma unroll
    for (int c = 0; c < HS; c++) {
        xv[c] = fmaxf(x[c] - m, 0.f) + 1e-9f;
        if (rowok && x[c] > m) { mk |= (1u << c); b += xv[c]; }
    }
    float B = b;
    #pragma unroll
    for (int o = 16; o; o >>= 1) B += __shfl_xor_sync(FULL, B, o);

    // ---- pack initial byte labels: byte j of word i = column 4i+j of this row.
    //      label = flat index (14*row + col) < 196 < 0xFF; background/pad = 0xFF.
    const unsigned base = lane * HS;
    unsigned w0, w1, w2, w3;
    {
        unsigned ww[4];
        #pragma unroll
        for (int i = 0; i < 4; i++) {
            unsigned v = 0;
            #pragma unroll
            for (int j = 0; j < 4; j++) {
                int c = 4 * i + j;
                unsigned byte = (c < HS && ((mk >> c) & 1u)) ? (base + c) : 0xFFu;
                v |= byte << (8 * j);
            }
            ww[i] = v;
        }
        w0 = ww[0]; w1 = ww[1]; w2 = ww[2]; w3 = ww[3];
    }
    // notmask: 0xFF bytes where background/pad (labels are never 0xFF)
    const unsigned n0 = __vcmpeq4(w0, FULL);
    const unsigned n1 = __vcmpeq4(w1, FULL);
    const unsigned n2 = __vcmpeq4(w2, FULL);
    const unsigned n3 = __vcmpeq4(w3, FULL);

    // ---- CC: byte-wise 8-neighbor min-propagation in registers, exact fixpoint
    for (;;) {
        // right neighbor into slot c (little-endian byte c = column c)
        unsigned sr0 = __funnelshift_r(w0, w1, 8);
        unsigned sr1 = __funnelshift_r(w1, w2, 8);
        unsigned sr2 = __funnelshift_r(w2, w3, 8);
        unsigned sr3 = __funnelshift_r(w3, FULL, 8);
        // left neighbor into slot c
        unsigned sl0 = __funnelshift_l(FULL, w0, 8);
        unsigned sl1 = __funnelshift_l(w0, w1, 8);
        unsigned sl2 = __funnelshift_l(w1, w2, 8);
        unsigned sl3 = __funnelshift_l(w2, w3, 8);
        // horizontal 3-min
        unsigned h0 = __vminu4(w0, __vminu4(sr0, sl0));
        unsigned h1 = __vminu4(w1, __vminu4(sr1, sl1));
        unsigned h2 = __vminu4(w2, __vminu4(sr2, sl2));
        unsigned h3 = __vminu4(w3, __vminu4(sr3, sl3));
        // vertical: rows r-1, r+1 (lane 0 shfl_up returns own = harmless;
        // lane 13 reads lane 14 which holds all-0xFF)
        unsigned u0 = __shfl_up_sync(FULL, h0, 1), d0 = __shfl_down_sync(FULL, h0, 1);
        unsigned u1 = __shfl_up_sync(FULL, h1, 1), d1 = __shfl_down_sync(FULL, h1, 1);
        unsigned u2 = __shfl_up_sync(FULL, h2, 1), d2 = __shfl_down_sync(FULL, h2, 1);
        unsigned u3 = __shfl_up_sync(FULL, h3, 1), d3 = __shfl_down_sync(FULL, h3, 1);
        unsigned t0 = __vminu4(h0, __vminu4(u0, d0)) | n0;
        unsigned t1 = __vminu4(h1, __vminu4(u1, d1)) | n1;
        unsigned t2 = __vminu4(h2, __vminu4(u2, d2)) | n2;
        unsigned t3 = __vminu4(h3, __vminu4(u3, d3)) | n3;

        unsigned ch = (t0 ^ w0) | (t1 ^ w1) | (t2 ^ w2) | (t3 ^ w3);
        w0 = t0; w1 = t1; w2 = t2; w3 = t3;
        if (!__any_sync(FULL, ch != 0u)) break;
    }

    // ---- per-component sums: spread shared atomics
    #pragma unroll
    for (int i = lane; i < PX; i += 32) PU[i] = 0.f;
    __syncwarp();

    #pragma unroll
    for (int c = 0; c < HS; c++) {
        if (rowok && ((mk >> c) & 1u)) {
            unsigned lb;
            if      (c < 4)  lb = (w0 >> (8 * c))        & 0xFFu;
            else if (c < 8)  lb = (w1 >> (8 * (c - 4)))  & 0xFFu;
            else if (c < 12) lb = (w2 >> (8 * (c - 8)))  & 0xFFu;
            else             lb = (w3 >> (8 * (c - 12))) & 0xFFu;
            atomicAdd(&PU[lb], xv[c]);
        }
    }
    __syncwarp();

    // ---- entropy at component roots (label == own flat index)
    float h = 0.f;
    const float invB = 1.0f / B;
    #pragma unroll
    for (int c = 0; c < HS; c++) {
        if (rowok && ((mk >> c) & 1u)) {
            unsigned lb;
            if      (c < 4)  lb = (w0 >> (8 * c))        & 0xFFu;
            else if (c < 8)  lb = (w1 >> (8 * (c - 4)))  & 0xFFu;
            else if (c < 12) lb = (w2 >> (8 * (c - 8)))  & 0xFFu;
            else             lb = (w3 >> (8 * (c - 12))) & 0xFFu;
            if (lb == base + c) {
                float pn = PU[lb] * invB;
                h -= pn * __logf(pn);
            }
        }
    }
    #pragma unroll
    for (int o = 16; o; o >>= 1) h += __shfl_xor_sync(FULL, h, o);
    if (lane == 0) atomicAdd(out, h * inv_n);
}

extern "C" void kernel_launch(void* const* d_in, const int* in_sizes, int n_in,
                              void* d_out, int out_size)
{
    const float* dq = (const float*)d_in[0];
    float* out = (float*)d_out;
    const int n = in_sizes[0] / (SEQ * SEQ);   // 128*12 = 1536

    cudaMemsetAsync(out, 0, sizeof(float));
    blob_loss_kernel<<<n, 32>>>(dq, out, 1.0f / (float)n, n);
}

// round 11
// speedup vs baseline: 1.8396x; 1.0741x over previous
#include <cuda_runtime.h>
#include <math.h>

#define HS   14
#define SEQ  197
#define FULL 0xFFFFFFFFu

__global__ __launch_bounds__(32) void blob_loss_kernel(
    const float* __restrict__ dot_qk,
    float* __restrict__ out,
    float inv_n)
{
    // labels live in "padded address space": addr = row*16 + col (<= 221).
    // Order-isomorphic to flat index (col < 14 < 16), so min-root identity matches.
    __shared__ unsigned char SLAB[2][256];
    __shared__ float PU[224];

    const int lane = threadIdx.x;
    const int task = blockIdx.x;

    const float* rowp  = dot_qk + (size_t)task * (SEQ * SEQ) + 1;
    const bool   rowok = (lane < HS);
    const float* myrow = rowp + lane * HS;

    // init label mirrors to 0xFF (incl. slot 255 for background gathers) and PU
    ((unsigned long long*)SLAB[0])[lane] = 0xFFFFFFFFFFFFFFFFull;
    ((unsigned long long*)SLAB[1])[lane] = 0xFFFFFFFFFFFFFFFFull;
    #pragma unroll
    for (int i = lane; i < 224; i += 32) PU[i] = 0.f;

    // ---- lane r owns row r: 14 register-resident floats
    float x[HS];
    float rs = 0.f;
    #pragma unroll
    for (int c = 0; c < HS; c++) {
        x[c] = rowok ? myrow[c] : 0.f;
        rs += x[c];
    }
    float s = rs;
    #pragma unroll
    for (int o = 16; o; o >>= 1) s += __shfl_xor_sync(FULL, s, o);
    const float m = s * (1.0f / 196.0f);

    // ---- mask, xv, B
    unsigned mk = 0;
    float xv[HS];
    float b = 0.f;
    #pragma unroll
    for (int c = 0; c < HS; c++) {
        xv[c] = fmaxf(x[c] - m, 0.f) + 1e-9f;
        if (rowok && x[c] > m) { mk |= (1u << c); b += xv[c]; }
    }
    float B = b;
    #pragma unroll
    for (int o = 16; o; o >>= 1) B += __shfl_xor_sync(FULL, B, o);

    // ---- pack initial byte labels (address space): byte j of word i = col 4i+j
    const unsigned abase = lane << 4;
    unsigned w0, w1, w2, w3;
    {
        unsigned ww[4];
        #pragma unroll
        for (int i = 0; i < 4; i++) {
            unsigned v = 0;
            #pragma unroll
            for (int j = 0; j < 4; j++) {
                int c = 4 * i + j;
                unsigned byte = (c < HS && ((mk >> c) & 1u)) ? (abase + c) : 0xFFu;
                v |= byte << (8 * j);
            }
            ww[i] = v;
        }
        w0 = ww[0]; w1 = ww[1]; w2 = ww[2]; w3 = ww[3];
    }
    const unsigned n0 = __vcmpeq4(w0, FULL);
    const unsigned n1 = __vcmpeq4(w1, FULL);
    const unsigned n2 = __vcmpeq4(w2, FULL);
    const unsigned n3 = __vcmpeq4(w3, FULL);

    // ---- CC: 1-step 8-neighbor min (registers) + pointer jump (shared byte gather)
    // Hard cap 196 iterations: min-propagation alone converges in <= 196 steps on a
    // 14x14 grid (reference uses exactly 196); the vote exits far earlier in practice.
    int bi = 0;
    for (int it = 0; it < 196; it++) {
        // horizontal 3-min (byte shifts across the 4-word row)
        unsigned sr0 = __funnelshift_r(w0, w1, 8);
        unsigned sr1 = __funnelshift_r(w1, w2, 8);
        unsigned sr2 = __funnelshift_r(w2, w3, 8);
        unsigned sr3 = __funnelshift_r(w3, FULL, 8);
        unsigned sl0 = __funnelshift_l(FULL, w0, 8);
        unsigned sl1 = __funnelshift_l(w0, w1, 8);
        unsigned sl2 = __funnelshift_l(w1, w2, 8);
        unsigned sl3 = __funnelshift_l(w2, w3, 8);
        unsigned h0 = __vminu4(w0, __vminu4(sr0, sl0));
        unsigned h1 = __vminu4(w1, __vminu4(sr1, sl1));
        unsigned h2 = __vminu4(w2, __vminu4(sr2, sl2));
        unsigned h3 = __vminu4(w3, __vminu4(sr3, sl3));
        // vertical min via lane shuffles
        unsigned u0 = __shfl_up_sync(FULL, h0, 1), d0 = __shfl_down_sync(FULL, h0, 1);
        unsigned u1 = __shfl_up_sync(FULL, h1, 1), d1 = __shfl_down_sync(FULL, h1, 1);
        unsigned u2 = __shfl_up_sync(FULL, h2, 1), d2 = __shfl_down_sync(FULL, h2, 1);
        unsigned u3 = __shfl_up_sync(FULL, h3, 1), d3 = __shfl_down_sync(FULL, h3, 1);
        unsigned t0 = __vminu4(h0, __vminu4(u0, d0)) | n0;
        unsigned t1 = __vminu4(h1, __vminu4(u1, d1)) | n1;
        unsigned t2 = __vminu4(h2, __vminu4(u2, d2)) | n2;
        unsigned t3 = __vminu4(h3, __vminu4(u3, d3)) | n3;

        // mirror row to shared (rows 0..13 -> bytes [lane*16, +16))
        if (rowok)
            *(uint4*)&SLAB[bi][abase] = make_uint4(t0, t1, t2, t3);
        __syncwarp();

        // pointer jump: lab = SLAB[lab] (background 0xFF -> SLAB[255] = 0xFF)
        unsigned g0 = FULL, g1 = FULL, g2 = FULL, g3 = FULL;
        if (rowok) {
            const unsigned char* S = SLAB[bi];
            unsigned b0  = S[t0 & 0xFFu],         b1  = S[(t0 >> 8) & 0xFFu];
            unsigned b2  = S[(t0 >> 16) & 0xFFu], b3  = S[t0 >> 24];
            unsigned b4  = S[t1 & 0xFFu],         b5  = S[(t1 >> 8) & 0xFFu];
            unsigned b6  = S[(t1 >> 16) & 0xFFu], b7  = S[t1 >> 24];
            unsigned b8  = S[t2 & 0xFFu],         b9  = S[(t2 >> 8) & 0xFFu];
            unsigned b10 = S[(t2 >> 16) & 0xFFu], b11 = S[t2 >> 24];
            unsigned b12 = S[t3 & 0xFFu],         b13 = S[(t3 >> 8) & 0xFFu];
            g0 = b0  | (b1  << 8) | (b2  << 16) | (b3  << 24);
            g1 = b4  | (b5  << 8) | (b6  << 16) | (b7  << 24);
            g2 = b8  | (b9  << 8) | (b10 << 16) | (b11 << 24);
            g3 = b12 | (b13 << 8) | 0xFFFF0000u;
        }

        unsigned ch = (g0 ^ w0) | (g1 ^ w1) | (g2 ^ w2) | (g3 ^ w3);
        w0 = g0; w1 = g1; w2 = g2; w3 = g3;
        bi ^= 1;
        if (!__any_sync(FULL, ch != 0u)) break;
    }

    // ---- per-component sums (labels are padded addresses, spread atomics)
    __syncwarp();
    #pragma unroll
    for (int c = 0; c < HS; c++) {
        if (rowok && ((mk >> c) & 1u)) {
            unsigned lb;
            if      (c < 4)  lb = (w0 >> (8 * c))        & 0xFFu;
            else if (c < 8)  lb = (w1 >> (8 * (c - 4)))  & 0xFFu;
            else if (c < 12) lb = (w2 >> (8 * (c - 8)))  & 0xFFu;
            else             lb = (w3 >> (8 * (c - 12))) & 0xFFu;
            atomicAdd(&PU[lb], xv[c]);
        }
    }
    __syncwarp();

    // ---- entropy at roots (label == own padded address)
    float h = 0.f;
    const float invB = 1.0f / B;
    #pragma unroll
    for (int c = 0; c < HS; c++) {
        if (rowok && ((mk >> c) & 1u)) {
            unsigned lb;
            if      (c < 4)  lb = (w0 >> (8 * c))        & 0xFFu;
            else if (c < 8)  lb = (w1 >> (8 * (c - 4)))  & 0xFFu;
            else if (c < 12) lb = (w2 >> (8 * (c - 8)))  & 0xFFu;
            else             lb = (w3 >> (8 * (c - 12))) & 0xFFu;
            if (lb == abase + c) {
                float pn = PU[lb] * invB;
                h -= pn * __logf(pn);
            }
        }
    }
    #pragma unroll
    for (int o = 16; o; o >>= 1) h += __shfl_xor_sync(FULL, h, o);
    if (lane == 0) atomicAdd(out, h * inv_n);
}

extern "C" void kernel_launch(void* const* d_in, const int* in_sizes, int n_in,
                              void* d_out, int out_size)
{
    const float* dq = (const float*)d_in[0];
    float* out = (float*)d_out;
    const int n = in_sizes[0] / (SEQ * SEQ);   // 128*12 = 1536

    cudaMemsetAsync(out, 0, sizeof(float));
    blob_loss_kernel<<<n, 32>>>(dq, out, 1.0f / (float)n);
}